// round 7
// baseline (speedup 1.0000x reference)
#include <cuda_runtime.h>
#include <cuda_bf16.h>
#include <math_constants.h>
#include <cstdint>

// ---------------- problem constants ----------------
constexpr int C_  = 64;
constexpr int L_  = 720;
constexpr int P_  = 336;
constexpr int P2_ = 168;
constexpr int M_  = 4096;   // B*C
constexpr int KPX = 768;    // 720 padded to 64

// ---------------- weight pool offsets (transposed [Nall][Kpad] bf16) -----
constexpr size_t OFF_WH  = 0;                 constexpr size_t SZ_WH  = 512  * 768;
constexpr size_t OFF_SSZ = OFF_WH  + SZ_WH;   constexpr size_t SZ_SSZ = 1024 * 512;
constexpr size_t OFF_XZ2 = OFF_SSZ + SZ_SSZ;  constexpr size_t SZ_XZ  = 1024 * 768;
constexpr size_t OFF_XZ3 = OFF_XZ2 + SZ_XZ;
constexpr size_t OFF_XZ4 = OFF_XZ3 + SZ_XZ;
constexpr size_t OFF_XZ5 = OFF_XZ4 + SZ_XZ;
constexpr size_t OFF_ZX0 = OFF_XZ5 + SZ_XZ;   constexpr size_t SZ_ZX  = 1440 * 512;
constexpr size_t OFF_ZX2 = OFF_ZX0 + SZ_ZX;
constexpr size_t OFF_ZX3 = OFF_ZX2 + SZ_ZX;
constexpr size_t OFF_ZY  = OFF_ZX3 + SZ_ZX;   constexpr size_t SZ_ZY  = 672 * 512;
constexpr size_t OFF_ROT = OFF_ZY  + SZ_ZY;   constexpr size_t SZ_ROT = 168 * 512;
constexpr size_t OFF_KOO = OFF_ROT + SZ_ROT;  constexpr size_t SZ_KOO = 672 * 512;
constexpr size_t POOL    = OFF_KOO + SZ_KOO;

// ---------------- static device scratch ----------------
__device__ __align__(128) __nv_bfloat16 g_wph[POOL];
__device__ __align__(128) __nv_bfloat16 g_wpl[POOL];
__device__ __align__(128) __nv_bfloat16 g_xh[M_ * KPX], g_xl[M_ * KPX];
__device__ __align__(128) __nv_bfloat16 g_hh[M_ * 512], g_hl[M_ * 512];
__device__ __align__(128) __nv_bfloat16 g_zh[M_ * 512], g_zl[M_ * 512];
__device__ __align__(128) float g_y [M_ * P_];
__device__ __align__(128) float g_th[M_ * P2_];

// ---------------- helpers ----------------
__device__ __forceinline__ uint32_t smem_u32(const void* p) {
    uint32_t a;
    asm("{ .reg .u64 t; cvta.to.shared.u64 t, %1; cvt.u32.u64 %0, t; }" : "=r"(a) : "l"(p));
    return a;
}
__device__ __forceinline__ uint32_t swz(uint32_t o) { return o ^ ((o >> 3) & 0x70); }

__device__ __forceinline__ void cp16(uint32_t dst, const void* src) {
    asm volatile("cp.async.cg.shared.global [%0], [%1], 16;" :: "r"(dst), "l"(src));
}
__device__ __forceinline__ void cp16z(uint32_t dst, const void* src, uint32_t sz) {
    asm volatile("cp.async.cg.shared.global [%0], [%1], 16, %2;"
                 :: "r"(dst), "l"(src), "r"(sz));
}
__device__ __forceinline__ void cp_commit() {
    asm volatile("cp.async.commit_group;" ::: "memory");
}
template <int N>
__device__ __forceinline__ void cp_wait() {
    asm volatile("cp.async.wait_group %0;" :: "n"(N) : "memory");
}
__device__ __forceinline__ void ldsm4(uint32_t* r, uint32_t a) {
    asm volatile("ldmatrix.sync.aligned.m8n8.x4.shared.b16 {%0,%1,%2,%3}, [%4];"
                 : "=r"(r[0]), "=r"(r[1]), "=r"(r[2]), "=r"(r[3]) : "r"(a));
}
__device__ __forceinline__ void mma_bf16(float* d, const uint32_t* a, const uint32_t* b) {
    asm volatile(
        "mma.sync.aligned.m16n8k16.row.col.f32.bf16.bf16.f32 "
        "{%0,%1,%2,%3}, {%4,%5,%6,%7}, {%8,%9}, {%0,%1,%2,%3};"
        : "+f"(d[0]), "+f"(d[1]), "+f"(d[2]), "+f"(d[3])
        : "r"(a[0]), "r"(a[1]), "r"(a[2]), "r"(a[3]), "r"(b[0]), "r"(b[1]));
}
__device__ __forceinline__ float gelu_tanh(float x) {
    float x3 = x * x * x;
    return 0.5f * x * (1.0f + tanhf(0.7978845608028654f * (x + 0.044715f * x3)));
}
__device__ __forceinline__ void split_bf(float v, __nv_bfloat16& h, __nv_bfloat16& l) {
    h = __float2bfloat16(v);
    l = __float2bfloat16(v - __bfloat162float(h));
}

// ---------------- prep: W [K][Nall] f32 -> [Nall][Kpad] bf16 hi/lo -------
__global__ void convert_w(const float* __restrict__ W, int K, int Nall, int Kpad,
                          __nv_bfloat16* __restrict__ Hi, __nv_bfloat16* __restrict__ Lo)
{
    __shared__ float t[32][33];
    int k0 = blockIdx.x * 32, n0 = blockIdx.y * 32;
    for (int i = threadIdx.y; i < 32; i += 8) {
        int k = k0 + i, n = n0 + threadIdx.x;
        t[i][threadIdx.x] = (k < K && n < Nall) ? W[(size_t)k * Nall + n] : 0.f;
    }
    __syncthreads();
    for (int i = threadIdx.y; i < 32; i += 8) {
        int n = n0 + i, k = k0 + threadIdx.x;
        if (n < Nall) {
            __nv_bfloat16 h, l; split_bf(t[threadIdx.x][i], h, l);
            Hi[(size_t)n * Kpad + k] = h;
            Lo[(size_t)n * Kpad + k] = l;
        }
    }
}

// ---------------- prep: x_bsd [64][720][64] -> xT hi/lo [4096][768] ------
__global__ void convert_x(const float* __restrict__ X,
                          __nv_bfloat16* __restrict__ Hi, __nv_bfloat16* __restrict__ Lo)
{
    __shared__ float t[32][33];
    int l0 = blockIdx.x * 32, c0 = blockIdx.y * 32, b = blockIdx.z;
    for (int i = threadIdx.y; i < 32; i += 8) {
        int l = l0 + i;
        t[i][threadIdx.x] = (l < L_) ? X[((size_t)b * L_ + l) * C_ + c0 + threadIdx.x] : 0.f;
    }
    __syncthreads();
    for (int i = threadIdx.y; i < 32; i += 8) {
        int c = c0 + i, l = l0 + threadIdx.x;
        __nv_bfloat16 h, lo; split_bf(t[threadIdx.x][i], h, lo);
        size_t o = (size_t)(b * 64 + c) * KPX + l;
        Hi[o] = h; Lo[o] = lo;
    }
}

// ---- fused mma.sync GEMM: 128x256 tile, 512 thr, 2-stage cp.async ----
enum { EP_GELU = 0, EP_TANHPI = 1, EP_AFF = 2, EP_FINAL = 3 };

template <int EPI>
__global__ __launch_bounds__(512)
void gemm_mma(const __nv_bfloat16* __restrict__ AH, const __nv_bfloat16* __restrict__ AL,
              int ldA, int KC,
              const __nv_bfloat16* __restrict__ WH, const __nv_bfloat16* __restrict__ WL,
              int ldW, int Nlog,
              const float* __restrict__ VinF,
              const __nv_bfloat16* __restrict__ VinH, const __nv_bfloat16* __restrict__ VinL,
              int ldV, float vscale,
              const float* __restrict__ Theta,
              const float* __restrict__ Ay, const float* __restrict__ By,
              __nv_bfloat16* __restrict__ OutH, __nv_bfloat16* __restrict__ OutL,
              float* __restrict__ OutF, int ldO)
{
    constexpr bool PAIR = (EPI == EP_AFF || EPI == EP_FINAL);
    constexpr int BN = 128;           // logical columns per block (PAIR: pairs)
    constexpr int RB = 256;           // B rows per stage
    constexpr int STAGE = 98304;      // 16K Ah + 16K Al + 32K Bh + 32K Bl

    extern __shared__ __align__(16) char smraw[];
    const uint32_t sbRaw = smem_u32(smraw);
    const uint32_t abU   = (sbRaw + 1023u) & ~1023u;
    char* ab = smraw + (abU - sbRaw);

    const int tid = threadIdx.x, wid = tid >> 5, lane = tid & 31;
    const int m0 = blockIdx.x * 128;
    const int n0 = blockIdx.y * (PAIR ? BN : RB);

    const int wm = wid >> 2, wn = wid & 3;    // 4x4 warp grid; tiles 32x64
    float acc[2][8][4];
#pragma unroll
    for (int a = 0; a < 2; ++a)
#pragma unroll
        for (int b = 0; b < 8; ++b)
#pragma unroll
            for (int c = 0; c < 4; ++c) acc[a][b][c] = 0.f;

    // ldmatrix per-lane constants
    const uint32_t aoffb = (uint32_t)(wm * 32 + (lane & 15)) * 128;
    const uint32_t boffb = (uint32_t)(wn * 64 + ((lane >> 4) & 1) * 8 + (lane & 7)) * 128;
    const uint32_t lx  = (lane & 7) * 16;
    const uint32_t acb = ((lane >> 4) & 1) * 16;
    const uint32_t bcb = ((lane >> 3) & 1) * 16;

    // ---- stage loader (cp.async), buffer = kt & 1 ----
    auto issue_stage = [&](int kt) {
        const uint32_t ub = abU + (uint32_t)(kt & 1) * STAGE;
#pragma unroll
        for (int i = 0; i < 2; ++i) {                   // A: 128 rows x 8 q
            int idx = tid + i * 512;
            int r = idx >> 3, q = idx & 7;
            uint32_t so = swz((uint32_t)(r * 128 + q * 16));
            size_t go = (size_t)(m0 + r) * ldA + kt * 64 + q * 8;
            cp16(ub + so,         AH + go);
            cp16(ub + 16384 + so, AL + go);
        }
#pragma unroll
        for (int i = 0; i < 4; ++i) {                   // B: 256 rows x 8 q
            int idx = tid + i * 512;
            int r = idx >> 3, q = idx & 7;
            int wr, ok;
            if (PAIR) {
                if (r < BN) { int j = n0 + r;      ok = j < Nlog; wr = j; }
                else        { int j = n0 + r - BN; ok = j < Nlog; wr = Nlog + j; }
            } else { wr = n0 + r; ok = wr < Nlog; }
            int wrc = ok ? wr : 0;
            uint32_t sz = ok ? 16u : 0u;
            uint32_t so = swz((uint32_t)(r * 128 + q * 16));
            size_t go = (size_t)wrc * ldW + kt * 64 + q * 8;
            cp16z(ub + 32768 + so, WH + go, sz);
            cp16z(ub + 65536 + so, WL + go, sz);
        }
        cp_commit();
    };

    // ---- compute one 64-k stage ----
    auto compute = [&](int buf) {
        const uint32_t uA  = abU + (uint32_t)buf * STAGE;
        const uint32_t uAl = uA + 16384, uB = uA + 32768, uBl = uA + 65536;
#pragma unroll
        for (int ks = 0; ks < 4; ++ks) {
            const uint32_t kb = ks * 32;
            const uint32_t axor = (kb + acb) ^ lx;
            const uint32_t bxor = (kb + bcb) ^ lx;
            uint32_t ah[2][4], al[2][4], bh[4][4], bl[4][4];
            ldsm4(ah[0], uA + aoffb + axor);
            ldsm4(ah[1], uA + aoffb + 2048 + axor);
#pragma unroll
            for (int t = 0; t < 4; ++t) ldsm4(bh[t], uB + boffb + t * 2048 + bxor);
#pragma unroll
            for (int mt = 0; mt < 2; ++mt)
#pragma unroll
                for (int nt = 0; nt < 8; ++nt)
                    mma_bf16(acc[mt][nt], ah[mt], &bh[nt >> 1][(nt & 1) * 2]);
            ldsm4(al[0], uAl + aoffb + axor);
            ldsm4(al[1], uAl + aoffb + 2048 + axor);
#pragma unroll
            for (int mt = 0; mt < 2; ++mt)
#pragma unroll
                for (int nt = 0; nt < 8; ++nt)
                    mma_bf16(acc[mt][nt], al[mt], &bh[nt >> 1][(nt & 1) * 2]);
#pragma unroll
            for (int t = 0; t < 4; ++t) ldsm4(bl[t], uBl + boffb + t * 2048 + bxor);
#pragma unroll
            for (int mt = 0; mt < 2; ++mt)
#pragma unroll
                for (int nt = 0; nt < 8; ++nt)
                    mma_bf16(acc[mt][nt], ah[mt], &bl[nt >> 1][(nt & 1) * 2]);
        }
    };

    // ---- 2-stage pipelined mainloop ----
    issue_stage(0);
    if (KC > 1) issue_stage(1);
#pragma unroll 1
    for (int kt = 0; kt < KC; ++kt) {
        if (kt + 1 < KC) cp_wait<1>(); else cp_wait<0>();
        __syncthreads();
        compute(kt & 1);
        if (kt + 2 < KC) { __syncthreads(); issue_stage(kt + 2); }
    }
    __syncthreads();

    // ---- dump accumulators to smem (aliases stage memory) ----
    constexpr int PITCH = 264;
    float* sAcc = reinterpret_cast<float*>(ab);
    {
        const int tr = lane >> 2, tc = (lane & 3) * 2;
#pragma unroll
        for (int mt = 0; mt < 2; ++mt)
#pragma unroll
            for (int nt = 0; nt < 8; ++nt) {
                int row = wm * 32 + mt * 16 + tr, col = wn * 64 + nt * 8 + tc;
                *reinterpret_cast<float2*>(&sAcc[row * PITCH + col]) =
                    make_float2(acc[mt][nt][0], acc[mt][nt][1]);
                *reinterpret_cast<float2*>(&sAcc[(row + 8) * PITCH + col]) =
                    make_float2(acc[mt][nt][2], acc[mt][nt][3]);
            }
    }
    __syncthreads();

    // ---- epilogue: lane -> column (coalesced gmem reads/writes) ----
    if (EPI == EP_GELU || EPI == EP_TANHPI) {
        for (int r = wid; r < 128; r += 16) {
            size_t ro = (size_t)(m0 + r) * ldO;
            for (int c = lane; c < RB; c += 32) {
                if (n0 + c >= Nlog) break;
                float a0 = sAcc[r * PITCH + c];
                float v = (EPI == EP_GELU) ? gelu_tanh(a0) : CUDART_PI_F * tanhf(a0);
                if (OutF) OutF[ro + n0 + c] = v;
                else { __nv_bfloat16 h, l; split_bf(v, h, l);
                       OutH[ro + n0 + c] = h; OutL[ro + n0 + c] = l; }
            }
        }
    } else if (EPI == EP_AFF) {
        for (int r = wid; r < 128; r += 16) {
            size_t rv = (size_t)(m0 + r) * ldV, ro = (size_t)(m0 + r) * ldO;
            for (int c = lane; c < BN; c += 32) {
                int n = n0 + c;
                if (n >= Nlog) break;
                float vin = VinF ? VinF[rv + n] * vscale
                                 : __bfloat162float(VinH[rv + n]) +
                                   __bfloat162float(VinL[rv + n]);
                float a0 = sAcc[r * PITCH + c], t0 = sAcc[r * PITCH + BN + c];
                float v = vin * __expf(tanhf(a0)) + t0;
                if (OutF) OutF[ro + n] = v;
                else { __nv_bfloat16 h, l; split_bf(v, h, l);
                       OutH[ro + n] = h; OutL[ro + n] = l; }
            }
        }
    } else { // EP_FINAL
        for (int r = wid; r < 128; r += 16) {
            int gm = m0 + r, cch = gm & 63, bb = gm >> 6;
            size_t rv = (size_t)gm * ldV;
            for (int cp = lane; cp < BN / 2; cp += 32) {
                int j = cp * 2, n = n0 + j;
                if (n >= Nlog) break;
                int p = n >> 1;
                float a0 = sAcc[r * PITCH + j],      a1 = sAcc[r * PITCH + j + 1];
                float t0 = sAcc[r * PITCH + BN + j], t1 = sAcc[r * PITCH + BN + j + 1];
                float th = Theta[(size_t)gm * P2_ + p], sn, cs;
                sincosf(th, &sn, &cs);
                float av = Ay[cch * P2_ + p], bv = By[cch * P2_ + p];
                float rn = rsqrtf(av * av + bv * bv);
                float ca = av * rn, cb = bv * rn;
                float2 yv = *reinterpret_cast<const float2*>(VinF + rv + n);
                float r1 = cs * yv.x - sn * yv.y, i1 = sn * yv.x + cs * yv.y;
                float r2 = ca * r1 - cb * i1, i2 = cb * r1 + ca * i1;
                float r3 = r2 * __expf(tanhf(a0)), i3 = i2 * __expf(tanhf(a1));
                float r4 = ca * r3 + cb * i3,  i4 = -cb * r3 + ca * i3;
                float r5 = cs * r4 + sn * i4,  i5 = -sn * r4 + cs * i4;
                OutF[((size_t)bb * P_ + n) * C_ + cch]     = r5 + t0;
                OutF[((size_t)bb * P_ + n + 1) * C_ + cch] = i5 + t1;
            }
        }
    }
}

// ---------------- host ----------------
constexpr int SMEMSZ = 2 * 98304 + 1024;

extern "C" void kernel_launch(void* const* d_in, const int* in_sizes, int n_in,
                              void* d_out, int out_size)
{
    (void)in_sizes; (void)n_in; (void)out_size;
    const float* x_bsd = (const float*)d_in[0];
    const float* z0    = (const float*)d_in[1];
    const float* y0    = (const float*)d_in[2];
    const float* a_y   = (const float*)d_in[16];
    const float* b_y   = (const float*)d_in[17];
    float* out = (float*)d_out;

    __nv_bfloat16 *wph, *wpl, *xh, *xl, *hh, *hl, *zh, *zl;
    float *y, *th;
    cudaGetSymbolAddress((void**)&wph, g_wph);
    cudaGetSymbolAddress((void**)&wpl, g_wpl);
    cudaGetSymbolAddress((void**)&xh, g_xh);  cudaGetSymbolAddress((void**)&xl, g_xl);
    cudaGetSymbolAddress((void**)&hh, g_hh);  cudaGetSymbolAddress((void**)&hl, g_hl);
    cudaGetSymbolAddress((void**)&zh, g_zh);  cudaGetSymbolAddress((void**)&zl, g_zl);
    cudaGetSymbolAddress((void**)&y,  g_y);   cudaGetSymbolAddress((void**)&th, g_th);

    static bool attr_done = false;
    if (!attr_done) {
        cudaFuncSetAttribute(gemm_mma<EP_GELU>,   cudaFuncAttributeMaxDynamicSharedMemorySize, SMEMSZ);
        cudaFuncSetAttribute(gemm_mma<EP_TANHPI>, cudaFuncAttributeMaxDynamicSharedMemorySize, SMEMSZ);
        cudaFuncSetAttribute(gemm_mma<EP_AFF>,    cudaFuncAttributeMaxDynamicSharedMemorySize, SMEMSZ);
        cudaFuncSetAttribute(gemm_mma<EP_FINAL>,  cudaFuncAttributeMaxDynamicSharedMemorySize, SMEMSZ);
        attr_done = true;
    }

    // ---- prep ----
    struct WS { int idx; int K, Nall, Kpad; size_t off; };
    const WS ws[12] = {
        {3, 720, 512, 768, OFF_WH},  {4, 512, 1024, 512, OFF_SSZ},
        {5, 720, 1024, 768, OFF_XZ2},{6, 720, 1024, 768, OFF_XZ3},
        {7, 720, 1024, 768, OFF_XZ4},{8, 720, 1024, 768, OFF_XZ5},
        {9, 512, 1440, 512, OFF_ZX0},{10,512, 1440, 512, OFF_ZX2},
        {11,512, 1440, 512, OFF_ZX3},{13,512, 672,  512, OFF_ZY},
        {14,512, 168,  512, OFF_ROT},{15,512, 672,  512, OFF_KOO},
    };
    for (int i = 0; i < 12; ++i) {
        dim3 g(ws[i].Kpad / 32, (ws[i].Nall + 31) / 32);
        convert_w<<<g, dim3(32, 8)>>>((const float*)d_in[ws[i].idx],
                                      ws[i].K, ws[i].Nall, ws[i].Kpad,
                                      wph + ws[i].off, wpl + ws[i].off);
    }
    convert_x<<<dim3(24, 2, 64), dim3(32, 8)>>>(x_bsd, xh, xl);

    // ---- GEMM chain (W_zx_v5 branch dead: skipped) ----
    const __nv_bfloat16* Z = nullptr; const float* ZF = nullptr;
    // 1) h = gelu(xT @ W_h)
    gemm_mma<EP_GELU><<<dim3(32, 2), 512, SMEMSZ>>>(
        xh, xl, 768, 12, wph + OFF_WH, wpl + OFF_WH, 768, 512,
        ZF, Z, Z, 0, 0.f, ZF, ZF, ZF, hh, hl, nullptr, 512);
    // 2) z = affine(0.1*z0 ; h @ W_ssz)
    gemm_mma<EP_AFF><<<dim3(32, 4), 512, SMEMSZ>>>(
        hh, hl, 512, 8, wph + OFF_SSZ, wpl + OFF_SSZ, 512, 512,
        z0, Z, Z, 512, 0.1f, ZF, ZF, ZF, zh, zl, nullptr, 512);
    // 3) x = affine(xT ; z @ W_zx_v0)
    gemm_mma<EP_AFF><<<dim3(32, 6), 512, SMEMSZ>>>(
        zh, zl, 512, 8, wph + OFF_ZX0, wpl + OFF_ZX0, 512, 720,
        ZF, xh, xl, 768, 1.f, ZF, ZF, ZF, xh, xl, nullptr, 768);
    // 4) z = affine(z ; x @ W_xz_v2)
    gemm_mma<EP_AFF><<<dim3(32, 4), 512, SMEMSZ>>>(
        xh, xl, 768, 12, wph + OFF_XZ2, wpl + OFF_XZ2, 768, 512,
        ZF, zh, zl, 512, 1.f, ZF, ZF, ZF, zh, zl, nullptr, 512);
    // 5) x = affine(x ; z @ W_zx_v2)
    gemm_mma<EP_AFF><<<dim3(32, 6), 512, SMEMSZ>>>(
        zh, zl, 512, 8, wph + OFF_ZX2, wpl + OFF_ZX2, 512, 720,
        ZF, xh, xl, 768, 1.f, ZF, ZF, ZF, xh, xl, nullptr, 768);
    // 6) z = affine(z ; x @ W_xz_v3)
    gemm_mma<EP_AFF><<<dim3(32, 4), 512, SMEMSZ>>>(
        xh, xl, 768, 12, wph + OFF_XZ3, wpl + OFF_XZ3, 768, 512,
        ZF, zh, zl, 512, 1.f, ZF, ZF, ZF, zh, zl, nullptr, 512);
    // 7) x = affine(x ; z @ W_zx_v3)
    gemm_mma<EP_AFF><<<dim3(32, 6), 512, SMEMSZ>>>(
        zh, zl, 512, 8, wph + OFF_ZX3, wpl + OFF_ZX3, 512, 720,
        ZF, xh, xl, 768, 1.f, ZF, ZF, ZF, xh, xl, nullptr, 768);
    // 8) z = affine(z ; x @ W_xz_v4)
    gemm_mma<EP_AFF><<<dim3(32, 4), 512, SMEMSZ>>>(
        xh, xl, 768, 12, wph + OFF_XZ4, wpl + OFF_XZ4, 768, 512,
        ZF, zh, zl, 512, 1.f, ZF, ZF, ZF, zh, zl, nullptr, 512);
    // 9) y = affine(0.1*y0 ; z @ W_zy_v4)   (f32 out)
    gemm_mma<EP_AFF><<<dim3(32, 3), 512, SMEMSZ>>>(
        zh, zl, 512, 8, wph + OFF_ZY, wpl + OFF_ZY, 512, 336,
        y0, Z, Z, 336, 0.1f, ZF, ZF, ZF, nullptr, nullptr, y, 336);
    // 10) z = affine(z ; x @ W_xz_v5)
    gemm_mma<EP_AFF><<<dim3(32, 4), 512, SMEMSZ>>>(
        xh, xl, 768, 12, wph + OFF_XZ5, wpl + OFF_XZ5, 768, 512,
        ZF, zh, zl, 512, 1.f, ZF, ZF, ZF, zh, zl, nullptr, 512);
    // 11) theta = pi*tanh(z @ W_rot)        (f32 out)
    gemm_mma<EP_TANHPI><<<dim3(32, 1), 512, SMEMSZ>>>(
        zh, zl, 512, 8, wph + OFF_ROT, wpl + OFF_ROT, 512, 168,
        ZF, Z, Z, 0, 0.f, ZF, ZF, ZF, nullptr, nullptr, th, 168);
    // 12) final: z @ W_koo -> scale/shift + rot/koop chain, transposed store
    gemm_mma<EP_FINAL><<<dim3(32, 3), 512, SMEMSZ>>>(
        zh, zl, 512, 8, wph + OFF_KOO, wpl + OFF_KOO, 512, 336,
        y, Z, Z, 336, 1.f, th, a_y, b_y, nullptr, nullptr, out, 0);
}

// round 8
// speedup vs baseline: 1.0657x; 1.0657x over previous
#include <cuda_runtime.h>
#include <cuda_bf16.h>
#include <math_constants.h>
#include <cstdint>

// ---------------- problem constants ----------------
constexpr int C_  = 64;
constexpr int L_  = 720;
constexpr int P_  = 336;
constexpr int P2_ = 168;
constexpr int M_  = 4096;   // B*C
constexpr int KPX = 768;    // 720 padded to 64

// ---------------- weight pool offsets (transposed [Nall][Kpad] bf16) -----
constexpr size_t OFF_WH  = 0;                 constexpr size_t SZ_WH  = 512  * 768;
constexpr size_t OFF_SSZ = OFF_WH  + SZ_WH;   constexpr size_t SZ_SSZ = 1024 * 512;
constexpr size_t OFF_XZ2 = OFF_SSZ + SZ_SSZ;  constexpr size_t SZ_XZ  = 1024 * 768;
constexpr size_t OFF_XZ3 = OFF_XZ2 + SZ_XZ;
constexpr size_t OFF_XZ4 = OFF_XZ3 + SZ_XZ;
constexpr size_t OFF_XZ5 = OFF_XZ4 + SZ_XZ;
constexpr size_t OFF_ZX0 = OFF_XZ5 + SZ_XZ;   constexpr size_t SZ_ZX  = 1440 * 512;
constexpr size_t OFF_ZX2 = OFF_ZX0 + SZ_ZX;
constexpr size_t OFF_ZX3 = OFF_ZX2 + SZ_ZX;
constexpr size_t OFF_ZY  = OFF_ZX3 + SZ_ZX;   constexpr size_t SZ_ZY  = 672 * 512;
constexpr size_t OFF_ROT = OFF_ZY  + SZ_ZY;   constexpr size_t SZ_ROT = 168 * 512;
constexpr size_t OFF_KOO = OFF_ROT + SZ_ROT;  constexpr size_t SZ_KOO = 672 * 512;
constexpr size_t POOL    = OFF_KOO + SZ_KOO;

// ---------------- static device scratch ----------------
__device__ __align__(128) __nv_bfloat16 g_wph[POOL];
__device__ __align__(128) __nv_bfloat16 g_wpl[POOL];
__device__ __align__(128) __nv_bfloat16 g_xh[M_ * KPX], g_xl[M_ * KPX];
__device__ __align__(128) __nv_bfloat16 g_hh[M_ * 512], g_hl[M_ * 512];
__device__ __align__(128) __nv_bfloat16 g_zh[M_ * 512], g_zl[M_ * 512];
__device__ __align__(128) float g_y [M_ * P_];
__device__ __align__(128) float g_th[M_ * P2_];

// ---------------- helpers ----------------
__device__ __forceinline__ uint32_t smem_u32(const void* p) {
    uint32_t a;
    asm("{ .reg .u64 t; cvta.to.shared.u64 t, %1; cvt.u32.u64 %0, t; }" : "=r"(a) : "l"(p));
    return a;
}
__device__ __forceinline__ uint32_t swz(uint32_t o) { return o ^ ((o >> 3) & 0x70); }

__device__ __forceinline__ void cp16(uint32_t dst, const void* src) {
    asm volatile("cp.async.cg.shared.global [%0], [%1], 16;" :: "r"(dst), "l"(src));
}
__device__ __forceinline__ void cp16z(uint32_t dst, const void* src, uint32_t sz) {
    asm volatile("cp.async.cg.shared.global [%0], [%1], 16, %2;"
                 :: "r"(dst), "l"(src), "r"(sz));
}
__device__ __forceinline__ void cp_commit() {
    asm volatile("cp.async.commit_group;" ::: "memory");
}
template <int N>
__device__ __forceinline__ void cp_wait() {
    asm volatile("cp.async.wait_group %0;" :: "n"(N) : "memory");
}
__device__ __forceinline__ void ldsm4(uint32_t* r, uint32_t a) {
    asm volatile("ldmatrix.sync.aligned.m8n8.x4.shared.b16 {%0,%1,%2,%3}, [%4];"
                 : "=r"(r[0]), "=r"(r[1]), "=r"(r[2]), "=r"(r[3]) : "r"(a));
}
__device__ __forceinline__ void mma_bf16(float* d, const uint32_t* a, const uint32_t* b) {
    asm volatile(
        "mma.sync.aligned.m16n8k16.row.col.f32.bf16.bf16.f32 "
        "{%0,%1,%2,%3}, {%4,%5,%6,%7}, {%8,%9}, {%0,%1,%2,%3};"
        : "+f"(d[0]), "+f"(d[1]), "+f"(d[2]), "+f"(d[3])
        : "r"(a[0]), "r"(a[1]), "r"(a[2]), "r"(a[3]), "r"(b[0]), "r"(b[1]));
}
__device__ __forceinline__ float gelu_tanh(float x) {
    float x3 = x * x * x;
    return 0.5f * x * (1.0f + tanhf(0.7978845608028654f * (x + 0.044715f * x3)));
}
__device__ __forceinline__ void split_bf(float v, __nv_bfloat16& h, __nv_bfloat16& l) {
    h = __float2bfloat16(v);
    l = __float2bfloat16(v - __bfloat162float(h));
}

// ---------------- prep: W [K][Nall] f32 -> [Nall][Kpad] bf16 hi/lo -------
__global__ void convert_w(const float* __restrict__ W, int K, int Nall, int Kpad,
                          __nv_bfloat16* __restrict__ Hi, __nv_bfloat16* __restrict__ Lo)
{
    __shared__ float t[32][33];
    int k0 = blockIdx.x * 32, n0 = blockIdx.y * 32;
    for (int i = threadIdx.y; i < 32; i += 8) {
        int k = k0 + i, n = n0 + threadIdx.x;
        t[i][threadIdx.x] = (k < K && n < Nall) ? W[(size_t)k * Nall + n] : 0.f;
    }
    __syncthreads();
    for (int i = threadIdx.y; i < 32; i += 8) {
        int n = n0 + i, k = k0 + threadIdx.x;
        if (n < Nall) {
            __nv_bfloat16 h, l; split_bf(t[threadIdx.x][i], h, l);
            Hi[(size_t)n * Kpad + k] = h;
            Lo[(size_t)n * Kpad + k] = l;
        }
    }
}

// ---------------- prep: x_bsd [64][720][64] -> xT hi/lo [4096][768] ------
__global__ void convert_x(const float* __restrict__ X,
                          __nv_bfloat16* __restrict__ Hi, __nv_bfloat16* __restrict__ Lo)
{
    __shared__ float t[32][33];
    int l0 = blockIdx.x * 32, c0 = blockIdx.y * 32, b = blockIdx.z;
    for (int i = threadIdx.y; i < 32; i += 8) {
        int l = l0 + i;
        t[i][threadIdx.x] = (l < L_) ? X[((size_t)b * L_ + l) * C_ + c0 + threadIdx.x] : 0.f;
    }
    __syncthreads();
    for (int i = threadIdx.y; i < 32; i += 8) {
        int c = c0 + i, l = l0 + threadIdx.x;
        __nv_bfloat16 h, lo; split_bf(t[threadIdx.x][i], h, lo);
        size_t o = (size_t)(b * 64 + c) * KPX + l;
        Hi[o] = h; Lo[o] = lo;
    }
}

// - fused mma.sync GEMM: 128x128 tile, 256 thr, k32 double-buffer, 2 CTA/SM -
enum { EP_GELU = 0, EP_TANHPI = 1, EP_AFF = 2, EP_FINAL = 3 };

template <int EPI>
__global__ __launch_bounds__(256, 2)
void gemm_mma(const __nv_bfloat16* __restrict__ AH, const __nv_bfloat16* __restrict__ AL,
              int ldA, int KC32,            // KC32 = K/32 chunks
              const __nv_bfloat16* __restrict__ WH, const __nv_bfloat16* __restrict__ WL,
              int ldW, int Nlog,
              const float* __restrict__ VinF,
              const __nv_bfloat16* __restrict__ VinH, const __nv_bfloat16* __restrict__ VinL,
              int ldV, float vscale,
              const float* __restrict__ Theta,
              const float* __restrict__ Ay, const float* __restrict__ By,
              __nv_bfloat16* __restrict__ OutH, __nv_bfloat16* __restrict__ OutL,
              float* __restrict__ OutF, int ldO)
{
    constexpr bool PAIR = (EPI == EP_AFF || EPI == EP_FINAL);
    constexpr int BN = 64;            // logical pair-columns per block (PAIR)
    constexpr int RB = 128;           // B rows per block

    extern __shared__ __align__(16) char smraw[];
    const uint32_t sbRaw = smem_u32(smraw);
    const uint32_t abU   = (sbRaw + 1023u) & ~1023u;
    char* ab = smraw + (abU - sbRaw);

    const int tid = threadIdx.x, wid = tid >> 5, lane = tid & 31;
    const int m0 = blockIdx.x * 128;
    const int n0 = blockIdx.y * (PAIR ? BN : RB);

    const int wm = wid >> 2, wn = wid & 3;   // 2 x 4 warp grid, 64x32 tiles
    float acc[4][4][4];
#pragma unroll
    for (int a = 0; a < 4; ++a)
#pragma unroll
        for (int b = 0; b < 4; ++b)
#pragma unroll
            for (int c = 0; c < 4; ++c) acc[a][b][c] = 0.f;

    // smem layout: Ah 16K | Al 16K | Bh 16K | Bl 16K  (128B rows = k64,
    // filled & consumed as two independent 64B k32 halves)
    const uint32_t uA = abU, uAl = abU + 16384, uB = abU + 32768, uBl = abU + 49152;

    // ldmatrix per-lane constants
    const uint32_t aoffb = (uint32_t)(wm * 64 + (lane & 15)) * 128;
    const uint32_t boffb = (uint32_t)(wn * 32 + ((lane >> 4) & 1) * 8 + (lane & 7)) * 128;
    const uint32_t lx  = (lane & 7) * 16;
    const uint32_t acb = ((lane >> 4) & 1) * 16;
    const uint32_t bcb = ((lane >> 3) & 1) * 16;

    // ---- chunk loader: k32 chunk c -> half (c&1) of the 128B rows ----
    auto issue_chunk = [&](int c) {
        const uint32_t hb = (uint32_t)(c & 1) * 64;
#pragma unroll
        for (int i = 0; i < 2; ++i) {          // A: 128 rows x 4 q
            int idx = tid + i * 256;
            int r = idx >> 2, q = idx & 3;
            uint32_t so = swz((uint32_t)(r * 128) + hb + q * 16);
            size_t go = (size_t)(m0 + r) * ldA + c * 32 + q * 8;
            cp16(uA  + so, AH + go);
            cp16(uAl + so, AL + go);
        }
#pragma unroll
        for (int i = 0; i < 2; ++i) {          // B: 128 rows x 4 q
            int idx = tid + i * 256;
            int r = idx >> 2, q = idx & 3;
            int wr, ok;
            if (PAIR) {
                if (r < BN) { int j = n0 + r;      ok = j < Nlog; wr = j; }
                else        { int j = n0 + r - BN; ok = j < Nlog; wr = Nlog + j; }
            } else { wr = n0 + r; ok = wr < Nlog; }
            int wrc = ok ? wr : 0;
            uint32_t sz = ok ? 16u : 0u;
            uint32_t so = swz((uint32_t)(r * 128) + hb + q * 16);
            size_t go = (size_t)wrc * ldW + c * 32 + q * 8;
            cp16z(uB  + so, WH + go, sz);
            cp16z(uBl + so, WL + go, sz);
        }
        cp_commit();
    };

    // ---- compute one k32 chunk ----
    auto compute = [&](int c) {
        const uint32_t hb = (uint32_t)(c & 1) * 64;
#pragma unroll
        for (int ks = 0; ks < 2; ++ks) {
            const uint32_t kb = hb + ks * 32;
            const uint32_t axor = (kb + acb) ^ lx;
            const uint32_t bxor = (kb + bcb) ^ lx;
            uint32_t ah[4][4], al[4][4], bh[2][4], bl[2][4];
#pragma unroll
            for (int t = 0; t < 4; ++t) ldsm4(ah[t], uA + aoffb + t * 2048 + axor);
            ldsm4(bh[0], uB + boffb + bxor);
            ldsm4(bh[1], uB + boffb + 2048 + bxor);
            ldsm4(bl[0], uBl + boffb + bxor);
            ldsm4(bl[1], uBl + boffb + 2048 + bxor);
#pragma unroll
            for (int mt = 0; mt < 4; ++mt)
#pragma unroll
                for (int nt = 0; nt < 4; ++nt)
                    mma_bf16(acc[mt][nt], ah[mt], &bh[nt >> 1][(nt & 1) * 2]);
#pragma unroll
            for (int mt = 0; mt < 4; ++mt)
#pragma unroll
                for (int nt = 0; nt < 4; ++nt)
                    mma_bf16(acc[mt][nt], ah[mt], &bl[nt >> 1][(nt & 1) * 2]);
#pragma unroll
            for (int t = 0; t < 4; ++t) ldsm4(al[t], uAl + aoffb + t * 2048 + axor);
#pragma unroll
            for (int mt = 0; mt < 4; ++mt)
#pragma unroll
                for (int nt = 0; nt < 4; ++nt)
                    mma_bf16(acc[mt][nt], al[mt], &bh[nt >> 1][(nt & 1) * 2]);
        }
    };

    // ---- k32 double-buffered mainloop ----
    issue_chunk(0);
    if (KC32 > 1) issue_chunk(1);
#pragma unroll 1
    for (int c = 0; c < KC32; ++c) {
        if (c + 1 < KC32) cp_wait<1>(); else cp_wait<0>();
        __syncthreads();
        compute(c);
        __syncthreads();
        if (c + 2 < KC32) issue_chunk(c + 2);
    }

    // ---- dump accumulators to smem (aliases stage memory) ----
    constexpr int PITCH = 132;
    float* sAcc = reinterpret_cast<float*>(ab);
    {
        const int tr = lane >> 2, tc = (lane & 3) * 2;
#pragma unroll
        for (int mt = 0; mt < 4; ++mt)
#pragma unroll
            for (int nt = 0; nt < 4; ++nt) {
                int row = wm * 64 + mt * 16 + tr, col = wn * 32 + nt * 8 + tc;
                *reinterpret_cast<float2*>(&sAcc[row * PITCH + col]) =
                    make_float2(acc[mt][nt][0], acc[mt][nt][1]);
                *reinterpret_cast<float2*>(&sAcc[(row + 8) * PITCH + col]) =
                    make_float2(acc[mt][nt][2], acc[mt][nt][3]);
            }
    }
    __syncthreads();

    // ---- epilogue: lane -> column (coalesced gmem) ----
    if (EPI == EP_GELU || EPI == EP_TANHPI) {
        for (int r = wid; r < 128; r += 8) {
            size_t ro = (size_t)(m0 + r) * ldO;
            for (int c = lane; c < RB; c += 32) {
                if (n0 + c >= Nlog) break;
                float a0 = sAcc[r * PITCH + c];
                float v = (EPI == EP_GELU) ? gelu_tanh(a0) : CUDART_PI_F * tanhf(a0);
                if (OutF) OutF[ro + n0 + c] = v;
                else { __nv_bfloat16 h, l; split_bf(v, h, l);
                       OutH[ro + n0 + c] = h; OutL[ro + n0 + c] = l; }
            }
        }
    } else if (EPI == EP_AFF) {
        for (int r = wid; r < 128; r += 8) {
            size_t rv = (size_t)(m0 + r) * ldV, ro = (size_t)(m0 + r) * ldO;
            for (int c = lane; c < BN; c += 32) {
                int n = n0 + c;
                if (n >= Nlog) break;
                float vin = VinF ? VinF[rv + n] * vscale
                                 : __bfloat162float(VinH[rv + n]) +
                                   __bfloat162float(VinL[rv + n]);
                float a0 = sAcc[r * PITCH + c], t0 = sAcc[r * PITCH + BN + c];
                float v = vin * __expf(tanhf(a0)) + t0;
                if (OutF) OutF[ro + n] = v;
                else { __nv_bfloat16 h, l; split_bf(v, h, l);
                       OutH[ro + n] = h; OutL[ro + n] = l; }
            }
        }
    } else { // EP_FINAL
        for (int r = wid; r < 128; r += 8) {
            int gm = m0 + r, cch = gm & 63, bb = gm >> 6;
            size_t rv = (size_t)gm * ldV;
            for (int cp = lane; cp < BN / 2; cp += 32) {
                int j = cp * 2, n = n0 + j;
                if (n >= Nlog) break;
                int p = n >> 1;
                float a0 = sAcc[r * PITCH + j],      a1 = sAcc[r * PITCH + j + 1];
                float t0 = sAcc[r * PITCH + BN + j], t1 = sAcc[r * PITCH + BN + j + 1];
                float th = Theta[(size_t)gm * P2_ + p], sn, cs;
                sincosf(th, &sn, &cs);
                float av = Ay[cch * P2_ + p], bv = By[cch * P2_ + p];
                float rn = rsqrtf(av * av + bv * bv);
                float ca = av * rn, cb = bv * rn;
                float2 yv = *reinterpret_cast<const float2*>(VinF + rv + n);
                float r1 = cs * yv.x - sn * yv.y, i1 = sn * yv.x + cs * yv.y;
                float r2 = ca * r1 - cb * i1, i2 = cb * r1 + ca * i1;
                float r3 = r2 * __expf(tanhf(a0)), i3 = i2 * __expf(tanhf(a1));
                float r4 = ca * r3 + cb * i3,  i4 = -cb * r3 + ca * i3;
                float r5 = cs * r4 + sn * i4,  i5 = -sn * r4 + cs * i4;
                OutF[((size_t)bb * P_ + n) * C_ + cch]     = r5 + t0;
                OutF[((size_t)bb * P_ + n + 1) * C_ + cch] = i5 + t1;
            }
        }
    }
}

// ---------------- host ----------------
constexpr int SMEMSZ = 69632;   // max(64K stage, 67.6K epi) + align slack

extern "C" void kernel_launch(void* const* d_in, const int* in_sizes, int n_in,
                              void* d_out, int out_size)
{
    (void)in_sizes; (void)n_in; (void)out_size;
    const float* x_bsd = (const float*)d_in[0];
    const float* z0    = (const float*)d_in[1];
    const float* y0    = (const float*)d_in[2];
    const float* a_y   = (const float*)d_in[16];
    const float* b_y   = (const float*)d_in[17];
    float* out = (float*)d_out;

    __nv_bfloat16 *wph, *wpl, *xh, *xl, *hh, *hl, *zh, *zl;
    float *y, *th;
    cudaGetSymbolAddress((void**)&wph, g_wph);
    cudaGetSymbolAddress((void**)&wpl, g_wpl);
    cudaGetSymbolAddress((void**)&xh, g_xh);  cudaGetSymbolAddress((void**)&xl, g_xl);
    cudaGetSymbolAddress((void**)&hh, g_hh);  cudaGetSymbolAddress((void**)&hl, g_hl);
    cudaGetSymbolAddress((void**)&zh, g_zh);  cudaGetSymbolAddress((void**)&zl, g_zl);
    cudaGetSymbolAddress((void**)&y,  g_y);   cudaGetSymbolAddress((void**)&th, g_th);

    static bool attr_done = false;
    if (!attr_done) {
        cudaFuncSetAttribute(gemm_mma<EP_GELU>,   cudaFuncAttributeMaxDynamicSharedMemorySize, SMEMSZ);
        cudaFuncSetAttribute(gemm_mma<EP_TANHPI>, cudaFuncAttributeMaxDynamicSharedMemorySize, SMEMSZ);
        cudaFuncSetAttribute(gemm_mma<EP_AFF>,    cudaFuncAttributeMaxDynamicSharedMemorySize, SMEMSZ);
        cudaFuncSetAttribute(gemm_mma<EP_FINAL>,  cudaFuncAttributeMaxDynamicSharedMemorySize, SMEMSZ);
        attr_done = true;
    }

    struct WS { int idx; int K, Nall, Kpad; size_t off; };
    const WS ws[12] = {
        {3, 720, 512, 768, OFF_WH},  {4, 512, 1024, 512, OFF_SSZ},
        {5, 720, 1024, 768, OFF_XZ2},{6, 720, 1024, 768, OFF_XZ3},
        {7, 720, 1024, 768, OFF_XZ4},{8, 720, 1024, 768, OFF_XZ5},
        {9, 512, 1440, 512, OFF_ZX0},{10,512, 1440, 512, OFF_ZX2},
        {11,512, 1440, 512, OFF_ZX3},{13,512, 672,  512, OFF_ZY},
        {14,512, 168,  512, OFF_ROT},{15,512, 672,  512, OFF_KOO},
    };
    auto conv = [&](int i) {
        dim3 g(ws[i].Kpad / 32, (ws[i].Nall + 31) / 32);
        convert_w<<<g, dim3(32, 8)>>>((const float*)d_in[ws[i].idx],
                                      ws[i].K, ws[i].Nall, ws[i].Kpad,
                                      wph + ws[i].off, wpl + ws[i].off);
    };

    const __nv_bfloat16* Z = nullptr; const float* ZF = nullptr;

    // Launch order: puts gemm_mma<EP_AFF> at index 5 so ncu (-s 5 -c 1)
    // captures a real GEMM instead of convert_w.
    conv(0);                                           // 0: W_h
    convert_x<<<dim3(24, 2, 64), dim3(32, 8)>>>(x_bsd, xh, xl);  // 1
    conv(1);                                           // 2: W_ssz
    conv(6);                                           // 3: W_zx_v0
    // 4: h = gelu(xT @ W_h)
    gemm_mma<EP_GELU><<<dim3(32, 4), 256, SMEMSZ>>>(
        xh, xl, 768, 24, wph + OFF_WH, wpl + OFF_WH, 768, 512,
        ZF, Z, Z, 0, 0.f, ZF, ZF, ZF, hh, hl, nullptr, 512);
    // 5: z = affine(0.1*z0 ; h @ W_ssz)   <-- ncu capture target
    gemm_mma<EP_AFF><<<dim3(32, 8), 256, SMEMSZ>>>(
        hh, hl, 512, 16, wph + OFF_SSZ, wpl + OFF_SSZ, 512, 512,
        z0, Z, Z, 512, 0.1f, ZF, ZF, ZF, zh, zl, nullptr, 512);
    // remaining converts (independent of the z/x chain)
    conv(2); conv(3); conv(4); conv(5); conv(7); conv(8);
    conv(9); conv(10); conv(11);
    // x = affine(xT ; z @ W_zx_v0)
    gemm_mma<EP_AFF><<<dim3(32, 12), 256, SMEMSZ>>>(
        zh, zl, 512, 16, wph + OFF_ZX0, wpl + OFF_ZX0, 512, 720,
        ZF, xh, xl, 768, 1.f, ZF, ZF, ZF, xh, xl, nullptr, 768);
    // z = affine(z ; x @ W_xz_v2)
    gemm_mma<EP_AFF><<<dim3(32, 8), 256, SMEMSZ>>>(
        xh, xl, 768, 24, wph + OFF_XZ2, wpl + OFF_XZ2, 768, 512,
        ZF, zh, zl, 512, 1.f, ZF, ZF, ZF, zh, zl, nullptr, 512);
    // x = affine(x ; z @ W_zx_v2)
    gemm_mma<EP_AFF><<<dim3(32, 12), 256, SMEMSZ>>>(
        zh, zl, 512, 16, wph + OFF_ZX2, wpl + OFF_ZX2, 512, 720,
        ZF, xh, xl, 768, 1.f, ZF, ZF, ZF, xh, xl, nullptr, 768);
    // z = affine(z ; x @ W_xz_v3)
    gemm_mma<EP_AFF><<<dim3(32, 8), 256, SMEMSZ>>>(
        xh, xl, 768, 24, wph + OFF_XZ3, wpl + OFF_XZ3, 768, 512,
        ZF, zh, zl, 512, 1.f, ZF, ZF, ZF, zh, zl, nullptr, 512);
    // x = affine(x ; z @ W_zx_v3)
    gemm_mma<EP_AFF><<<dim3(32, 12), 256, SMEMSZ>>>(
        zh, zl, 512, 16, wph + OFF_ZX3, wpl + OFF_ZX3, 512, 720,
        ZF, xh, xl, 768, 1.f, ZF, ZF, ZF, xh, xl, nullptr, 768);
    // z = affine(z ; x @ W_xz_v4)
    gemm_mma<EP_AFF><<<dim3(32, 8), 256, SMEMSZ>>>(
        xh, xl, 768, 24, wph + OFF_XZ4, wpl + OFF_XZ4, 768, 512,
        ZF, zh, zl, 512, 1.f, ZF, ZF, ZF, zh, zl, nullptr, 512);
    // y = affine(0.1*y0 ; z @ W_zy_v4)   (f32 out)
    gemm_mma<EP_AFF><<<dim3(32, 6), 256, SMEMSZ>>>(
        zh, zl, 512, 16, wph + OFF_ZY, wpl + OFF_ZY, 512, 336,
        y0, Z, Z, 336, 0.1f, ZF, ZF, ZF, nullptr, nullptr, y, 336);
    // z = affine(z ; x @ W_xz_v5)
    gemm_mma<EP_AFF><<<dim3(32, 8), 256, SMEMSZ>>>(
        xh, xl, 768, 24, wph + OFF_XZ5, wpl + OFF_XZ5, 768, 512,
        ZF, zh, zl, 512, 1.f, ZF, ZF, ZF, zh, zl, nullptr, 512);
    // theta = pi*tanh(z @ W_rot)         (f32 out)
    gemm_mma<EP_TANHPI><<<dim3(32, 2), 256, SMEMSZ>>>(
        zh, zl, 512, 16, wph + OFF_ROT, wpl + OFF_ROT, 512, 168,
        ZF, Z, Z, 0, 0.f, ZF, ZF, ZF, nullptr, nullptr, th, 168);
    // final: z @ W_koo -> scale/shift + rot/koop chain, transposed store
    gemm_mma<EP_FINAL><<<dim3(32, 6), 256, SMEMSZ>>>(
        zh, zl, 512, 16, wph + OFF_KOO, wpl + OFF_KOO, 512, 336,
        y, Z, Z, 336, 1.f, th, a_y, b_y, nullptr, nullptr, out, 0);
}